// round 2
// baseline (speedup 1.0000x reference)
#include <cuda_runtime.h>
#include <cuda_bf16.h>
#include <cstdint>
#include <cstddef>

#define NROWS 8192          // BATCH*NODE
#define DIM   128
#define FEAT  256           // 2*DIM
#define KDIM  8192
#define EPSC  1e-5f

// ---------------- scratch (__device__ globals: no allocations allowed) ----------------
__device__ float          g_X  [NROWS * DIM];          // elu output, row-major (8192x128)
__device__ __nv_bfloat16  g_Xhi[DIM * NROWS];          // transposed [feature][row] = [128][8192]
__device__ __nv_bfloat16  g_Xlo[DIM * NROWS];
__device__ float          g_Lx [NROWS * DIM];          // L @ X, row-major
__device__ float          g_Y  [NROWS * DIM];          // block0 output
__device__ float          g_stats[2 * FEAT];           // [0:256) colsum, [256:512) colsumsq

__device__ __forceinline__ void split_bf16(float v, __nv_bfloat16& h, __nv_bfloat16& l) {
    h = __float2bfloat16(v);
    l = __float2bfloat16(v - __bfloat162float(h));
}

// ---------------- kernel 1: ELU + bf16 hi/lo split + transpose ----------------
// src == nullptr -> read g_Y. Writes g_X (fp32 row-major), g_Xhi/g_Xlo (bf16, [feat][row]).
// Block (0,0) also zeroes g_stats for the upcoming stats pass.
__global__ void elu_split_kernel(const float* __restrict__ src) {
    const float* __restrict__ s = src ? src : g_Y;
    __shared__ float tile[32][33];
    int r0 = blockIdx.x * 32, c0 = blockIdx.y * 32;
    int tx = threadIdx.x, ty = threadIdx.y;
#pragma unroll
    for (int i = 0; i < 4; i++) {
        int r = r0 + ty + i * 8, c = c0 + tx;
        float v = s[(size_t)r * DIM + c];
        v = v > 0.f ? v : expm1f(v);
        g_X[(size_t)r * DIM + c] = v;
        tile[ty + i * 8][tx] = v;
    }
    __syncthreads();
#pragma unroll
    for (int i = 0; i < 4; i++) {
        int c = c0 + ty + i * 8;   // feature
        int r = r0 + tx;           // row
        float v = tile[tx][ty + i * 8];
        __nv_bfloat16 h, l; split_bf16(v, h, l);
        g_Xhi[(size_t)c * NROWS + r] = h;
        g_Xlo[(size_t)c * NROWS + r] = l;
    }
    if (blockIdx.x == 0 && blockIdx.y == 0) {
        int tid = ty * 32 + tx;    // 0..255
        g_stats[tid] = 0.f;
        g_stats[tid + FEAT] = 0.f;
    }
}

// ---------------- kernel 2: big GEMM  Lx = L @ X  (bf16 3-pass split, fp32 accum) --------
#define BM 64
#define BK 32
#define BN 128
#define SA_STR 40   // bf16 units per A smem row  (conflict-free: bank = 20*row + t)
#define SB_STR 40   // bf16 units per B smem row

__device__ __forceinline__ void mma16816(float* acc, const uint32_t* a, uint32_t b0, uint32_t b1) {
    asm volatile(
        "mma.sync.aligned.m16n8k16.row.col.f32.bf16.bf16.f32 "
        "{%0,%1,%2,%3}, {%4,%5,%6,%7}, {%8,%9}, {%0,%1,%2,%3};\n"
        : "+f"(acc[0]), "+f"(acc[1]), "+f"(acc[2]), "+f"(acc[3])
        : "r"(a[0]), "r"(a[1]), "r"(a[2]), "r"(a[3]), "r"(b0), "r"(b1));
}

__global__ __launch_bounds__(256) void big_gemm_kernel(const float* __restrict__ L) {
    __shared__ __nv_bfloat16 sAhi[BM * SA_STR];
    __shared__ __nv_bfloat16 sAlo[BM * SA_STR];
    __shared__ __nv_bfloat16 sBhi[BN * SB_STR];
    __shared__ __nv_bfloat16 sBlo[BN * SB_STR];

    const int tid  = threadIdx.x;
    const int lane = tid & 31, wid = tid >> 5;
    const int g  = lane >> 2;
    const int t2 = (lane & 3) * 2;
    const int wm = (wid & 3) * 16;     // 4 warps over M (16 rows each)
    const int wn = (wid >> 2) * 64;    // 2 warps over N (64 cols each)
    const long mBase = (long)blockIdx.x * BM;

    // per-thread global-load coordinates (2 float4 A loads, 2 uint4 B loads per matrix)
    int arow[2], ac4[2], bn_[2], bseg[2];
#pragma unroll
    for (int i = 0; i < 2; i++) {
        int idx = tid + i * 256;
        arow[i] = idx >> 3; ac4[i] = idx & 7;     // A: 64 rows x 8 float4
        bn_[i]  = idx >> 2; bseg[i] = idx & 3;    // B: 128 rows x 4 uint4
    }

    float4 aReg[2]; uint4 bhReg[2], blReg[2];

    auto ldg = [&](int k0) {
#pragma unroll
        for (int i = 0; i < 2; i++)
            aReg[i] = *(const float4*)(L + (mBase + arow[i]) * (long)KDIM + k0 + ac4[i] * 4);
#pragma unroll
        for (int i = 0; i < 2; i++) {
            size_t off = (size_t)bn_[i] * NROWS + k0 + bseg[i] * 8;
            bhReg[i] = *(const uint4*)(g_Xhi + off);
            blReg[i] = *(const uint4*)(g_Xlo + off);
        }
    };

    auto sts = [&]() {
#pragma unroll
        for (int i = 0; i < 2; i++) {
            float v[4] = {aReg[i].x, aReg[i].y, aReg[i].z, aReg[i].w};
            uint32_t h[4], l[4];
#pragma unroll
            for (int j = 0; j < 4; j++) {
                __nv_bfloat16 hh, ll; split_bf16(v[j], hh, ll);
                h[j] = (uint32_t)__bfloat16_as_ushort(hh);
                l[j] = (uint32_t)__bfloat16_as_ushort(ll);
            }
            int off = arow[i] * SA_STR + ac4[i] * 4;
            *(uint2*)&sAhi[off] = make_uint2(h[0] | (h[1] << 16), h[2] | (h[3] << 16));
            *(uint2*)&sAlo[off] = make_uint2(l[0] | (l[1] << 16), l[2] | (l[3] << 16));
            int boff = bn_[i] * SB_STR + bseg[i] * 8;
            *(uint4*)&sBhi[boff] = bhReg[i];
            *(uint4*)&sBlo[boff] = blReg[i];
        }
    };

    float acc[8][4];
#pragma unroll
    for (int n = 0; n < 8; n++)
#pragma unroll
        for (int j = 0; j < 4; j++) acc[n][j] = 0.f;

    const int rA0 = (wm + g)     * SA_STR;
    const int rA1 = (wm + g + 8) * SA_STR;

    ldg(0);
    for (int kc = 0; kc < KDIM / BK; kc++) {
        sts();
        __syncthreads();
        if (kc + 1 < KDIM / BK) ldg((kc + 1) * BK);

#pragma unroll
        for (int ks = 0; ks < 2; ks++) {
            const int kk = ks * 16 + t2;
            uint32_t ah[4], al[4];
            ah[0] = *(const uint32_t*)&sAhi[rA0 + kk];
            ah[1] = *(const uint32_t*)&sAhi[rA1 + kk];
            ah[2] = *(const uint32_t*)&sAhi[rA0 + kk + 8];
            ah[3] = *(const uint32_t*)&sAhi[rA1 + kk + 8];
            al[0] = *(const uint32_t*)&sAlo[rA0 + kk];
            al[1] = *(const uint32_t*)&sAlo[rA1 + kk];
            al[2] = *(const uint32_t*)&sAlo[rA0 + kk + 8];
            al[3] = *(const uint32_t*)&sAlo[rA1 + kk + 8];
#pragma unroll
            for (int nt = 0; nt < 8; nt++) {
                const int nb = (wn + nt * 8 + g) * SB_STR + kk;
                uint32_t bh0 = *(const uint32_t*)&sBhi[nb];
                uint32_t bh1 = *(const uint32_t*)&sBhi[nb + 8];
                uint32_t bl0 = *(const uint32_t*)&sBlo[nb];
                uint32_t bl1 = *(const uint32_t*)&sBlo[nb + 8];
                mma16816(acc[nt], ah, bh0, bh1);   // hi*hi
                mma16816(acc[nt], ah, bl0, bl1);   // hi*lo
                mma16816(acc[nt], al, bh0, bh1);   // lo*hi
            }
        }
        __syncthreads();
    }

    const long r0 = mBase + wm + g;
    const long r1 = r0 + 8;
#pragma unroll
    for (int nt = 0; nt < 8; nt++) {
        int c = wn + nt * 8 + t2;
        *(float2*)&g_Lx[r0 * DIM + c] = make_float2(acc[nt][0], acc[nt][1]);
        *(float2*)&g_Lx[r1 * DIM + c] = make_float2(acc[nt][2], acc[nt][3]);
    }
}

// ---------------- kernel 3: per-feature column sums / sumsq of [X | Lx] ----------------
__global__ void stats_kernel() {
    int b = blockIdx.x;          // 32 blocks: 16 per matrix
    int mat = b >> 4;
    int rbase = (b & 15) * 512;
    const float* __restrict__ M = mat ? g_Lx : g_X;
    int c = threadIdx.x;         // 128 threads = columns
    float s = 0.f, s2 = 0.f;
#pragma unroll 4
    for (int r = 0; r < 512; r++) {
        float v = M[(size_t)(rbase + r) * DIM + c];
        s += v; s2 += v * v;
    }
    atomicAdd(&g_stats[mat * DIM + c], s);
    atomicAdd(&g_stats[FEAT + mat * DIM + c], s2);
}

// ---------------- kernel 4: BN folded into Linear: out = h @ (W*s)^T + (b + W t) --------
// h = [X | Lx] (conceptual concat); out==nullptr -> g_Y. residual added if non-null.
__global__ __launch_bounds__(256) void small_gemm_kernel(
    const float* __restrict__ gamma, const float* __restrict__ beta,
    const float* __restrict__ W,     const float* __restrict__ bias,
    const float* __restrict__ residual, float* __restrict__ outp)
{
    float* __restrict__ out = outp ? outp : g_Y;
    __shared__ float sS[FEAT], sT[FEAT], sC[DIM];
    __shared__ float sH[64][33];
    __shared__ float sW[128][33];

    const int tid = threadIdx.x;
    {
        int f = tid;  // exactly 256 threads
        float mu  = g_stats[f] * (1.f / NROWS);
        float var = g_stats[FEAT + f] * (1.f / NROWS) - mu * mu;
        float inv = rsqrtf(var + EPSC);
        float s = gamma[f] * inv;
        sS[f] = s;
        sT[f] = beta[f] - mu * s;
    }
    __syncthreads();
    if (tid < DIM) {
        float cb = bias[tid];
        for (int f = 0; f < FEAT; f++) cb += sT[f] * W[tid * FEAT + f];
        sC[tid] = cb;
    }
    __syncthreads();

    float acc[4][8];
#pragma unroll
    for (int r = 0; r < 4; r++)
#pragma unroll
        for (int c = 0; c < 8; c++) acc[r][c] = 0.f;

    const int rBase = blockIdx.x * 64;
    const int ti = tid >> 4, tj = tid & 15;

    for (int fc = 0; fc < FEAT; fc += 32) {
#pragma unroll
        for (int i = 0; i < 8; i++) {
            int idx = tid + i * 256;
            int row = idx >> 5, f = idx & 31;
            int gf = fc + f;
            float v = (gf < DIM) ? g_X [(size_t)(rBase + row) * DIM + gf]
                                 : g_Lx[(size_t)(rBase + row) * DIM + (gf - DIM)];
            sH[row][f] = v;
        }
#pragma unroll
        for (int i = 0; i < 16; i++) {
            int idx = tid + i * 256;
            int d = idx >> 5, f = idx & 31;
            int gf = fc + f;
            sW[d][f] = W[d * FEAT + gf] * sS[gf];
        }
        __syncthreads();
#pragma unroll
        for (int f = 0; f < 32; f++) {
            float hv[4], wv[8];
#pragma unroll
            for (int r = 0; r < 4; r++) hv[r] = sH[ti * 4 + r][f];
#pragma unroll
            for (int c = 0; c < 8; c++) wv[c] = sW[tj * 8 + c][f];
#pragma unroll
            for (int r = 0; r < 4; r++)
#pragma unroll
                for (int c = 0; c < 8; c++) acc[r][c] += hv[r] * wv[c];
        }
        __syncthreads();
    }

#pragma unroll
    for (int r = 0; r < 4; r++)
#pragma unroll
        for (int c = 0; c < 8; c++) {
            int row = rBase + ti * 4 + r;
            int col = tj * 8 + c;
            float o = acc[r][c] + sC[col];
            if (residual) o += residual[(size_t)row * DIM + col];
            out[(size_t)row * DIM + col] = o;
        }
}

// ---------------- launch ----------------
extern "C" void kernel_launch(void* const* d_in, const int* in_sizes, int n_in,
                              void* d_out, int out_size)
{
    const float* L      = (const float*)d_in[0];
    // d_in[1] = mask (unused in forward)
    const float* inputs = (const float*)d_in[2];
    const float* bn0_g  = (const float*)d_in[3];
    const float* bn0_b  = (const float*)d_in[4];
    const float* fc0_w  = (const float*)d_in[5];
    const float* fc0_b  = (const float*)d_in[6];
    const float* bn1_g  = (const float*)d_in[7];
    const float* bn1_b  = (const float*)d_in[8];
    const float* fc1_w  = (const float*)d_in[9];
    const float* fc1_b  = (const float*)d_in[10];
    float* out = (float*)d_out;

    dim3 eg(NROWS / 32, DIM / 32), eb(32, 8);

    // ---- block 0 ----
    elu_split_kernel<<<eg, eb>>>(inputs);                 // X = elu(inputs); also zeroes stats
    big_gemm_kernel<<<NROWS / BM, 256>>>(L);              // Lx = L @ X
    stats_kernel<<<32, 128>>>();                          // column stats of [X | Lx]
    small_gemm_kernel<<<NROWS / 64, 256>>>(bn0_g, bn0_b, fc0_w, fc0_b,
                                           nullptr, nullptr);   // -> g_Y

    // ---- block 1 ----
    elu_split_kernel<<<eg, eb>>>(nullptr);                // X = elu(g_Y); zeroes stats
    big_gemm_kernel<<<NROWS / BM, 256>>>(L);
    stats_kernel<<<32, 128>>>();
    small_gemm_kernel<<<NROWS / 64, 256>>>(bn1_g, bn1_b, fc1_w, fc1_b,
                                           inputs, out);  // + residual -> d_out
}